// round 2
// baseline (speedup 1.0000x reference)
#include <cuda_runtime.h>
#include <cuda_bf16.h>
#include <math.h>

// Problem constants
#define S     2048
#define HID   2048
#define NH    32
#define NKV   8
#define HD    64
#define WINDOW 1024
#define KVW   (NKV*HD)     // 512
#define SCALE 0.125f       // 1/sqrt(64)

// ---------------- scratch (no allocation allowed) ----------------
__device__ float g_Q[S * HID];      // 16 MB
__device__ float g_K[S * KVW];      //  4 MB
__device__ float g_V[S * KVW];      //  4 MB
__device__ float g_O[S * HID];      // 16 MB

// ---------------- GEMM: C[M,N] = A[M,K] @ B[K,N], fp32 ----------------
// 128x128 block tile, BK=16, 256 threads, 8x8 micro-tile.
// Double-buffered: prefetch k-tile t+1 into registers while computing t.
__global__ __launch_bounds__(256) void gemm_kernel(
    const float* __restrict__ A, const float* __restrict__ B,
    float* __restrict__ C, int M, int N, int K)
{
    __shared__ float As[2][16][128];   // As[buf][k][m] (transposed on load)
    __shared__ float Bs[2][16][128];   // Bs[buf][k][n]

    const int tid = threadIdx.x;
    const int bm = blockIdx.y, bn = blockIdx.x;
    const int tx = tid & 15, ty = tid >> 4;
    const int m0 = ty * 8, n0 = tx * 8;

    const float* Ab = A + (size_t)bm * 128 * K;
    const float* Bb = B + bn * 128;

    // Per-thread load coordinates (2 float4 each for A and B)
    const int ar0 = tid >> 1,               ac0 = (tid & 1) << 3;       // A rows 0..127, col 0/8
    const int br0 = tid >> 4,               bc0 = (tid & 15) << 3;      // B rows 0..15, col 0..120
    // each thread loads A[ar0][ac0..ac0+7] (2 float4) and B[br0][bc0..bc0+7]

    float acc[8][8];
    #pragma unroll
    for (int i = 0; i < 8; i++)
        #pragma unroll
        for (int j = 0; j < 8; j++) acc[i][j] = 0.f;

    // ---- load first tile into buffer 0 ----
    float4 pa0, pa1, pb0, pb1;
    pa0 = *(const float4*)&Ab[(size_t)ar0 * K + 0 + ac0];
    pa1 = *(const float4*)&Ab[(size_t)ar0 * K + 0 + ac0 + 4];
    pb0 = *(const float4*)&Bb[(size_t)(0 + br0) * N + bc0];
    pb1 = *(const float4*)&Bb[(size_t)(0 + br0) * N + bc0 + 4];

    As[0][ac0 + 0][ar0] = pa0.x; As[0][ac0 + 1][ar0] = pa0.y;
    As[0][ac0 + 2][ar0] = pa0.z; As[0][ac0 + 3][ar0] = pa0.w;
    As[0][ac0 + 4][ar0] = pa1.x; As[0][ac0 + 5][ar0] = pa1.y;
    As[0][ac0 + 6][ar0] = pa1.z; As[0][ac0 + 7][ar0] = pa1.w;
    *(float4*)&Bs[0][br0][bc0]     = pb0;
    *(float4*)&Bs[0][br0][bc0 + 4] = pb1;
    __syncthreads();

    int buf = 0;
    for (int k0 = 0; k0 < K; k0 += 16) {
        const bool has_next = (k0 + 16) < K;
        // ---- prefetch next tile into registers (latency overlapped w/ FMAs) ----
        if (has_next) {
            int kn = k0 + 16;
            pa0 = *(const float4*)&Ab[(size_t)ar0 * K + kn + ac0];
            pa1 = *(const float4*)&Ab[(size_t)ar0 * K + kn + ac0 + 4];
            pb0 = *(const float4*)&Bb[(size_t)(kn + br0) * N + bc0];
            pb1 = *(const float4*)&Bb[(size_t)(kn + br0) * N + bc0 + 4];
        }

        // ---- compute on current buffer ----
        #pragma unroll
        for (int kk = 0; kk < 16; kk++) {
            float a[8], b[8];
            *(float4*)&a[0] = *(float4*)&As[buf][kk][m0];
            *(float4*)&a[4] = *(float4*)&As[buf][kk][m0 + 4];
            *(float4*)&b[0] = *(float4*)&Bs[buf][kk][n0];
            *(float4*)&b[4] = *(float4*)&Bs[buf][kk][n0 + 4];
            #pragma unroll
            for (int i = 0; i < 8; i++)
                #pragma unroll
                for (int j = 0; j < 8; j++)
                    acc[i][j] = fmaf(a[i], b[j], acc[i][j]);
        }

        // ---- store prefetched regs into alternate buffer ----
        if (has_next) {
            int nb = buf ^ 1;
            As[nb][ac0 + 0][ar0] = pa0.x; As[nb][ac0 + 1][ar0] = pa0.y;
            As[nb][ac0 + 2][ar0] = pa0.z; As[nb][ac0 + 3][ar0] = pa0.w;
            As[nb][ac0 + 4][ar0] = pa1.x; As[nb][ac0 + 5][ar0] = pa1.y;
            As[nb][ac0 + 6][ar0] = pa1.z; As[nb][ac0 + 7][ar0] = pa1.w;
            *(float4*)&Bs[nb][br0][bc0]     = pb0;
            *(float4*)&Bs[nb][br0][bc0 + 4] = pb1;
            __syncthreads();
            buf = nb;
        }
    }

    #pragma unroll
    for (int i = 0; i < 8; i++) {
        int row = bm * 128 + m0 + i;
        float* cp = &C[(size_t)row * N + bn * 128 + n0];
        *(float4*)&cp[0] = make_float4(acc[i][0], acc[i][1], acc[i][2], acc[i][3]);
        *(float4*)&cp[4] = make_float4(acc[i][4], acc[i][5], acc[i][6], acc[i][7]);
    }
}

// ---------------- RoPE (in place on g_Q and g_K) ----------------
// layout: [s][h*64 + d]; pair (d, d+32), angle = s * base^(-d/32)
#define LOG2_ROPE_BASE 18.931568569324174f   // log2(500000)
__global__ __launch_bounds__(256) void rope_kernel()
{
    int idx = blockIdx.x * blockDim.x + threadIdx.x;
    const int qtot = S * NH * (HD / 2);      // 2,097,152
    const int ktot = S * NKV * (HD / 2);     //   524,288
    if (idx >= qtot + ktot) return;

    float* buf; int s, off, d;
    if (idx < qtot) {
        d = idx & 31; int h = (idx >> 5) & 31; s = idx >> 10;
        buf = g_Q; off = s * HID + h * 64 + d;
    } else {
        int j = idx - qtot;
        d = j & 31; int h = (j >> 5) & 7; s = j >> 8;
        buf = g_K; off = s * KVW + h * 64 + d;
    }
    float inv = exp2f(-(float)d * (LOG2_ROPE_BASE / 32.0f));
    float ph  = (float)s * inv;
    float sn, c;
    sincosf(ph, &sn, &c);
    float x1 = buf[off], x2 = buf[off + 32];
    buf[off]      = x1 * c - x2 * sn;
    buf[off + 32] = x2 * c + x1 * sn;
}

// ---------------- Flash attention, sliding window ----------------
// grid (S/64, NH), 256 threads. Per block: 64 q rows of one head.
// Smem layouts (all transposed for float4/broadcast inner loops):
//   Qs[d][r], Ks[d][c], Vs[c][d], Ps[c][r], each 64 x SPAD.
#define SPAD 68
#define ATTN_SMEM (4 * 64 * SPAD * 4)

__global__ __launch_bounds__(256) void attn_kernel()
{
    extern __shared__ float sm[];
    float* Qs = sm;
    float* Ks = sm + 64 * SPAD;
    float* Vs = sm + 2 * 64 * SPAD;
    float* Ps = sm + 3 * 64 * SPAD;

    const int tid = threadIdx.x;
    const int h  = blockIdx.y;
    const int qb = blockIdx.x << 6;
    const int kvh = h >> 2;                  // NH/NKV = 4
    const int tx = tid & 15, ty = tid >> 4;  // 16x16 threads, 4x4 micro

    // Load Q tile transposed: Qs[d][r]
    for (int v = tid; v < 64 * 16; v += 256) {
        int r = v >> 4, d4 = (v & 15) << 2;
        float4 q4 = *(const float4*)&g_Q[(size_t)(qb + r) * HID + h * 64 + d4];
        Qs[(d4 + 0) * SPAD + r] = q4.x; Qs[(d4 + 1) * SPAD + r] = q4.y;
        Qs[(d4 + 2) * SPAD + r] = q4.z; Qs[(d4 + 3) * SPAD + r] = q4.w;
    }

    float m_i[4], l_i[4], acc[4][4];
    #pragma unroll
    for (int i = 0; i < 4; i++) {
        m_i[i] = -1e30f; l_i[i] = 0.f;
        #pragma unroll
        for (int j = 0; j < 4; j++) acc[i][j] = 0.f;
    }

    const int t0 = max(0, qb - (WINDOW - 1)) >> 6;
    const int t1 = qb >> 6;

    for (int t = t0; t <= t1; ++t) {
        const int kb = t << 6;
        // Load K transposed (Ks[d][c]) and V natural (Vs[c][d])
        for (int v = tid; v < 64 * 16; v += 256) {
            int c = v >> 4, d4 = (v & 15) << 2;
            size_t base = (size_t)(kb + c) * KVW + kvh * 64 + d4;
            float4 k4 = *(const float4*)&g_K[base];
            Ks[(d4 + 0) * SPAD + c] = k4.x; Ks[(d4 + 1) * SPAD + c] = k4.y;
            Ks[(d4 + 2) * SPAD + c] = k4.z; Ks[(d4 + 3) * SPAD + c] = k4.w;
            *(float4*)&Vs[c * SPAD + d4] = *(const float4*)&g_V[base];
        }
        __syncthreads();

        // Scores: S = Q @ K^T  (4x4 micro)
        float sc[4][4];
        #pragma unroll
        for (int i = 0; i < 4; i++)
            #pragma unroll
            for (int j = 0; j < 4; j++) sc[i][j] = 0.f;

        #pragma unroll 8
        for (int d = 0; d < 64; ++d) {
            float4 qv = *(float4*)&Qs[d * SPAD + ty * 4];
            float4 kv = *(float4*)&Ks[d * SPAD + tx * 4];
            float qa[4] = {qv.x, qv.y, qv.z, qv.w};
            float ka[4] = {kv.x, kv.y, kv.z, kv.w};
            #pragma unroll
            for (int i = 0; i < 4; i++)
                #pragma unroll
                for (int j = 0; j < 4; j++)
                    sc[i][j] = fmaf(qa[i], ka[j], sc[i][j]);
        }

        // Mask + online softmax (row reduce over 16 lanes, width-16 shfl)
        #pragma unroll
        for (int i = 0; i < 4; i++) {
            int rg = qb + ty * 4 + i;
            float rmax = -1e30f;
            #pragma unroll
            for (int j = 0; j < 4; j++) {
                int cg = kb + tx * 4 + j;
                float sv = (cg <= rg && cg >= rg - (WINDOW - 1)) ? sc[i][j] * SCALE : -1e30f;
                sc[i][j] = sv;
                rmax = fmaxf(rmax, sv);
            }
            #pragma unroll
            for (int o = 8; o >= 1; o >>= 1)
                rmax = fmaxf(rmax, __shfl_xor_sync(0xffffffffu, rmax, o, 16));

            float mnew = fmaxf(m_i[i], rmax);
            float corr = expf(m_i[i] - mnew);
            float rsum = 0.f;
            #pragma unroll
            for (int j = 0; j < 4; j++) {
                float p = (sc[i][j] > -1e29f) ? expf(sc[i][j] - mnew) : 0.f;
                sc[i][j] = p;
                rsum += p;
            }
            #pragma unroll
            for (int o = 8; o >= 1; o >>= 1)
                rsum += __shfl_xor_sync(0xffffffffu, rsum, o, 16);

            l_i[i] = l_i[i] * corr + rsum;
            m_i[i] = mnew;
            #pragma unroll
            for (int j = 0; j < 4; j++) acc[i][j] *= corr;
        }

        // Store P transposed: Ps[c][r]
        #pragma unroll
        for (int j = 0; j < 4; j++)
            *(float4*)&Ps[(tx * 4 + j) * SPAD + ty * 4] =
                make_float4(sc[0][j], sc[1][j], sc[2][j], sc[3][j]);
        __syncthreads();

        // acc += P @ V
        #pragma unroll 8
        for (int c = 0; c < 64; ++c) {
            float4 pv = *(float4*)&Ps[c * SPAD + ty * 4];
            float4 vv = *(float4*)&Vs[c * SPAD + tx * 4];
            float pa[4] = {pv.x, pv.y, pv.z, pv.w};
            float va[4] = {vv.x, vv.y, vv.z, vv.w};
            #pragma unroll
            for (int i = 0; i < 4; i++)
                #pragma unroll
                for (int j = 0; j < 4; j++)
                    acc[i][j] = fmaf(pa[i], va[j], acc[i][j]);
        }
        __syncthreads();   // before next tile overwrites Ks/Vs
    }

    // Epilogue: normalize, write g_O[s][h*64+d]
    #pragma unroll
    for (int i = 0; i < 4; i++) {
        float inv = 1.f / l_i[i];
        *(float4*)&g_O[(size_t)(qb + ty * 4 + i) * HID + h * 64 + tx * 4] =
            make_float4(acc[i][0] * inv, acc[i][1] * inv, acc[i][2] * inv, acc[i][3] * inv);
    }
}

// ---------------- launch ----------------
extern "C" void kernel_launch(void* const* d_in, const int* in_sizes, int n_in,
                              void* d_out, int out_size)
{
    const float* X  = (const float*)d_in[0];
    const float* Wq = (const float*)d_in[1];
    const float* Wk = (const float*)d_in[2];
    const float* Wv = (const float*)d_in[3];
    const float* Wo = (const float*)d_in[4];
    float* out = (float*)d_out;

    float *gQ, *gK, *gV, *gO;
    cudaGetSymbolAddress((void**)&gQ, g_Q);
    cudaGetSymbolAddress((void**)&gK, g_K);
    cudaGetSymbolAddress((void**)&gV, g_V);
    cudaGetSymbolAddress((void**)&gO, g_O);

    cudaFuncSetAttribute(attn_kernel,
                         cudaFuncAttributeMaxDynamicSharedMemorySize, ATTN_SMEM);

    // QKV projections
    gemm_kernel<<<dim3(HID / 128, S / 128), 256>>>(X, Wq, gQ, S, HID, HID);
    gemm_kernel<<<dim3(KVW / 128, S / 128), 256>>>(X, Wk, gK, S, KVW, HID);
    gemm_kernel<<<dim3(KVW / 128, S / 128), 256>>>(X, Wv, gV, S, KVW, HID);

    // RoPE on Q and K
    {
        int total = S * NH * (HD / 2) + S * NKV * (HD / 2);
        rope_kernel<<<(total + 255) / 256, 256>>>();
    }

    // Sliding-window flash attention
    attn_kernel<<<dim3(S / 64, NH), 256, ATTN_SMEM>>>();

    // Output projection
    gemm_kernel<<<dim3(HID / 128, S / 128), 256>>>(gO, Wo, out, S, HID, HID);
}

// round 6
// speedup vs baseline: 2.2481x; 2.2481x over previous
#include <cuda_runtime.h>
#include <cuda_bf16.h>
#include <math.h>
#include <stdint.h>

// Problem constants
#define S     2048
#define HID   2048
#define NH    32
#define NKV   8
#define HD    64
#define WINDOW 1024
#define KVW   (NKV*HD)     // 512
#define SCALE 0.125f       // 1/sqrt(64)

// ---------------- scratch (no allocation allowed) ----------------
__device__ float g_Q[S * HID];      // 16 MB
__device__ float g_K[S * KVW];      //  4 MB
__device__ float g_V[S * KVW];      //  4 MB
__device__ float g_O[S * HID];      // 16 MB

// ---------------- tf32 helpers ----------------
__device__ __forceinline__ uint32_t f2tf32(float x) {
    uint32_t u;
    asm("cvt.rna.tf32.f32 %0, %1;" : "=r"(u) : "f"(x));
    return u;
}
__device__ __forceinline__ float f2tf32f(float x) {
    return __uint_as_float(f2tf32(x));
}
__device__ __forceinline__ void mma_tf32(float* c,
    uint32_t a0, uint32_t a1, uint32_t a2, uint32_t a3,
    uint32_t b0, uint32_t b1)
{
    asm volatile(
        "mma.sync.aligned.m16n8k8.row.col.f32.tf32.tf32.f32 "
        "{%0,%1,%2,%3}, {%4,%5,%6,%7}, {%8,%9}, {%0,%1,%2,%3};"
        : "+f"(c[0]), "+f"(c[1]), "+f"(c[2]), "+f"(c[3])
        : "r"(a0), "r"(a1), "r"(a2), "r"(a3), "r"(b0), "r"(b1));
}

// ---------------- GEMM: C[M,N] = A[M,K] @ B[K,N], tf32 tensor-core ----
// Block 128x128, BK=16, 256 threads (8 warps, 2x4), warp tile 64x32.
#define GSTRIDE 136
__global__ __launch_bounds__(256) void gemm_tc(
    const float* __restrict__ A, const float* __restrict__ B,
    float* __restrict__ C, int M, int N, int K)
{
    __shared__ float As[2][16][GSTRIDE];   // As[buf][k][m]
    __shared__ float Bs[2][16][GSTRIDE];   // Bs[buf][k][n]

    const int tid  = threadIdx.x;
    const int wid  = tid >> 5, lane = tid & 31;
    const int g    = lane >> 2, tig = lane & 3;
    const int wm   = (wid >> 2) << 6;      // 0 / 64
    const int wn   = (wid & 3) << 5;       // 0,32,64,96

    const int bm = blockIdx.y, bn = blockIdx.x;
    const float* Ab = A + (size_t)bm * 128 * K;
    const float* Bb = B + bn * 128;

    const int ar = tid >> 1, ac = (tid & 1) << 3;
    const int br = tid >> 4, bc = (tid & 15) << 3;

    float acc[4][4][4];
    #pragma unroll
    for (int i = 0; i < 4; i++)
        #pragma unroll
        for (int j = 0; j < 4; j++)
            #pragma unroll
            for (int r = 0; r < 4; r++) acc[i][j][r] = 0.f;

    float4 pa0, pa1, pb0, pb1;

    pa0 = *(const float4*)&Ab[(size_t)ar * K + ac];
    pa1 = *(const float4*)&Ab[(size_t)ar * K + ac + 4];
    pb0 = *(const float4*)&Bb[(size_t)br * N + bc];
    pb1 = *(const float4*)&Bb[(size_t)br * N + bc + 4];

    As[0][ac + 0][ar] = f2tf32f(pa0.x); As[0][ac + 1][ar] = f2tf32f(pa0.y);
    As[0][ac + 2][ar] = f2tf32f(pa0.z); As[0][ac + 3][ar] = f2tf32f(pa0.w);
    As[0][ac + 4][ar] = f2tf32f(pa1.x); As[0][ac + 5][ar] = f2tf32f(pa1.y);
    As[0][ac + 6][ar] = f2tf32f(pa1.z); As[0][ac + 7][ar] = f2tf32f(pa1.w);
    Bs[0][br][bc + 0] = f2tf32f(pb0.x); Bs[0][br][bc + 1] = f2tf32f(pb0.y);
    Bs[0][br][bc + 2] = f2tf32f(pb0.z); Bs[0][br][bc + 3] = f2tf32f(pb0.w);
    Bs[0][br][bc + 4] = f2tf32f(pb1.x); Bs[0][br][bc + 5] = f2tf32f(pb1.y);
    Bs[0][br][bc + 6] = f2tf32f(pb1.z); Bs[0][br][bc + 7] = f2tf32f(pb1.w);
    __syncthreads();

    int buf = 0;
    for (int k0 = 0; k0 < K; k0 += 16) {
        const bool has_next = (k0 + 16) < K;
        if (has_next) {
            int kn = k0 + 16;
            pa0 = *(const float4*)&Ab[(size_t)ar * K + kn + ac];
            pa1 = *(const float4*)&Ab[(size_t)ar * K + kn + ac + 4];
            pb0 = *(const float4*)&Bb[(size_t)(kn + br) * N + bc];
            pb1 = *(const float4*)&Bb[(size_t)(kn + br) * N + bc + 4];
        }

        #pragma unroll
        for (int ks = 0; ks < 16; ks += 8) {
            uint32_t af[4][4], bf[4][2];
            #pragma unroll
            for (int mt = 0; mt < 4; mt++) {
                int m = wm + (mt << 4) + g;
                af[mt][0] = __float_as_uint(As[buf][ks + tig    ][m]);
                af[mt][1] = __float_as_uint(As[buf][ks + tig    ][m + 8]);
                af[mt][2] = __float_as_uint(As[buf][ks + tig + 4][m]);
                af[mt][3] = __float_as_uint(As[buf][ks + tig + 4][m + 8]);
            }
            #pragma unroll
            for (int nt = 0; nt < 4; nt++) {
                int n = wn + (nt << 3) + g;
                bf[nt][0] = __float_as_uint(Bs[buf][ks + tig    ][n]);
                bf[nt][1] = __float_as_uint(Bs[buf][ks + tig + 4][n]);
            }
            #pragma unroll
            for (int mt = 0; mt < 4; mt++)
                #pragma unroll
                for (int nt = 0; nt < 4; nt++)
                    mma_tf32(acc[mt][nt],
                             af[mt][0], af[mt][1], af[mt][2], af[mt][3],
                             bf[nt][0], bf[nt][1]);
        }

        if (has_next) {
            int nb = buf ^ 1;
            As[nb][ac + 0][ar] = f2tf32f(pa0.x); As[nb][ac + 1][ar] = f2tf32f(pa0.y);
            As[nb][ac + 2][ar] = f2tf32f(pa0.z); As[nb][ac + 3][ar] = f2tf32f(pa0.w);
            As[nb][ac + 4][ar] = f2tf32f(pa1.x); As[nb][ac + 5][ar] = f2tf32f(pa1.y);
            As[nb][ac + 6][ar] = f2tf32f(pa1.z); As[nb][ac + 7][ar] = f2tf32f(pa1.w);
            Bs[nb][br][bc + 0] = f2tf32f(pb0.x); Bs[nb][br][bc + 1] = f2tf32f(pb0.y);
            Bs[nb][br][bc + 2] = f2tf32f(pb0.z); Bs[nb][br][bc + 3] = f2tf32f(pb0.w);
            Bs[nb][br][bc + 4] = f2tf32f(pb1.x); Bs[nb][br][bc + 5] = f2tf32f(pb1.y);
            Bs[nb][br][bc + 6] = f2tf32f(pb1.z); Bs[nb][br][bc + 7] = f2tf32f(pb1.w);
            __syncthreads();
            buf = nb;
        }
    }

    #pragma unroll
    for (int mt = 0; mt < 4; mt++) {
        int r0 = bm * 128 + wm + (mt << 4) + g;
        #pragma unroll
        for (int nt = 0; nt < 4; nt++) {
            int c = bn * 128 + wn + (nt << 3) + (tig << 1);
            *(float2*)&C[(size_t)r0 * N + c] =
                make_float2(acc[mt][nt][0], acc[mt][nt][1]);
            *(float2*)&C[(size_t)(r0 + 8) * N + c] =
                make_float2(acc[mt][nt][2], acc[mt][nt][3]);
        }
    }
}

// ---------------- RoPE (in place on g_Q and g_K) ----------------
#define LOG2_ROPE_BASE 18.931568569324174f   // log2(500000)
__global__ __launch_bounds__(256) void rope_kernel()
{
    int idx = blockIdx.x * blockDim.x + threadIdx.x;
    const int qtot = S * NH * (HD / 2);
    const int ktot = S * NKV * (HD / 2);
    if (idx >= qtot + ktot) return;

    float* buf; int s, off, d;
    if (idx < qtot) {
        d = idx & 31; int h = (idx >> 5) & 31; s = idx >> 10;
        buf = g_Q; off = s * HID + h * 64 + d;
    } else {
        int j = idx - qtot;
        d = j & 31; int h = (j >> 5) & 7; s = j >> 8;
        buf = g_K; off = s * KVW + h * 64 + d;
    }
    float inv = exp2f(-(float)d * (LOG2_ROPE_BASE / 32.0f));
    float ph  = (float)s * inv;
    float sn, c;
    sincosf(ph, &sn, &c);
    float x1 = buf[off], x2 = buf[off + 32];
    buf[off]      = x1 * c - x2 * sn;
    buf[off + 32] = x2 * c + x1 * sn;
}

// ---------------- Flash attention, sliding window, tf32 tensor-core ---
// grid (S/64, NH), 128 threads (4 warps). Warp w owns q rows 16w..16w+15.
// Smem (stride 72 floats => mma fragment LDS conflict-free):
//   Qs[d][r] (pre-scaled by 1/8), Ks[d][c], Vs[c][d], Ps[c][r]
#define ASPAD 72
#define ATTN_SMEM (4 * 64 * ASPAD * 4)   // 73728 bytes

__global__ __launch_bounds__(128) void attn_tc()
{
    extern __shared__ float sm[];
    float* Qs = sm;
    float* Ks = sm + 64 * ASPAD;
    float* Vs = sm + 2 * 64 * ASPAD;
    float* Ps = sm + 3 * 64 * ASPAD;

    const int tid = threadIdx.x;
    const int h   = blockIdx.y;
    const int qb  = blockIdx.x << 6;
    const int kvh = h >> 2;                 // NH/NKV = 4
    const int wid = tid >> 5, lane = tid & 31;
    const int g = lane >> 2, tig = lane & 3;
    const int m0 = wid << 4;                // 0,16,32,48

    // Load Q tile transposed + prescaled: Qs[d][r] = tf32(q * SCALE)
    for (int v = tid; v < 64 * 16; v += 128) {
        int r = v >> 4, d4 = (v & 15) << 2;
        float4 q4 = *(const float4*)&g_Q[(size_t)(qb + r) * HID + h * 64 + d4];
        Qs[(d4 + 0) * ASPAD + r] = f2tf32f(q4.x * SCALE);
        Qs[(d4 + 1) * ASPAD + r] = f2tf32f(q4.y * SCALE);
        Qs[(d4 + 2) * ASPAD + r] = f2tf32f(q4.z * SCALE);
        Qs[(d4 + 3) * ASPAD + r] = f2tf32f(q4.w * SCALE);
    }

    float m_i[2] = {-1e30f, -1e30f};
    float l_i[2] = {0.f, 0.f};
    float oacc[8][4];
    #pragma unroll
    for (int nt = 0; nt < 8; nt++)
        #pragma unroll
        for (int r = 0; r < 4; r++) oacc[nt][r] = 0.f;

    const int t0 = max(0, qb - (WINDOW - 1)) >> 6;
    const int t1 = qb >> 6;
    const int r0g = qb + m0 + g, r1g = r0g + 8;

    for (int t = t0; t <= t1; ++t) {
        const int kb = t << 6;
        // Load K transposed (Ks[d][c]) and V natural (Vs[c][d]), tf32
        for (int v = tid; v < 64 * 16; v += 128) {
            int c = v >> 4, d4 = (v & 15) << 2;
            size_t base = (size_t)(kb + c) * KVW + kvh * 64 + d4;
            float4 k4 = *(const float4*)&g_K[base];
            Ks[(d4 + 0) * ASPAD + c] = f2tf32f(k4.x);
            Ks[(d4 + 1) * ASPAD + c] = f2tf32f(k4.y);
            Ks[(d4 + 2) * ASPAD + c] = f2tf32f(k4.z);
            Ks[(d4 + 3) * ASPAD + c] = f2tf32f(k4.w);
            float4 v4 = *(const float4*)&g_V[base];
            float4 vt;
            vt.x = f2tf32f(v4.x); vt.y = f2tf32f(v4.y);
            vt.z = f2tf32f(v4.z); vt.w = f2tf32f(v4.w);
            *(float4*)&Vs[c * ASPAD + d4] = vt;
        }
        __syncthreads();

        // ---- S = Q @ K^T (pre-scaled) ----
        float sacc[8][4];
        #pragma unroll
        for (int nt = 0; nt < 8; nt++)
            #pragma unroll
            for (int r = 0; r < 4; r++) sacc[nt][r] = 0.f;

        #pragma unroll
        for (int ks = 0; ks < 64; ks += 8) {
            uint32_t a0 = __float_as_uint(Qs[(ks + tig    ) * ASPAD + m0 + g]);
            uint32_t a1 = __float_as_uint(Qs[(ks + tig    ) * ASPAD + m0 + g + 8]);
            uint32_t a2 = __float_as_uint(Qs[(ks + tig + 4) * ASPAD + m0 + g]);
            uint32_t a3 = __float_as_uint(Qs[(ks + tig + 4) * ASPAD + m0 + g + 8]);
            #pragma unroll
            for (int nt = 0; nt < 8; nt++) {
                uint32_t b0 = __float_as_uint(Ks[(ks + tig    ) * ASPAD + nt * 8 + g]);
                uint32_t b1 = __float_as_uint(Ks[(ks + tig + 4) * ASPAD + nt * 8 + g]);
                mma_tf32(sacc[nt], a0, a1, a2, a3, b0, b1);
            }
        }

        // ---- mask (boundary tiles only) ----
        if ((t == t1) || (kb < qb - 960)) {
            #pragma unroll
            for (int nt = 0; nt < 8; nt++) {
                int c0 = kb + nt * 8 + (tig << 1), c1 = c0 + 1;
                if (c0 > r0g || c0 < r0g - (WINDOW - 1)) sacc[nt][0] = -1e30f;
                if (c1 > r0g || c1 < r0g - (WINDOW - 1)) sacc[nt][1] = -1e30f;
                if (c0 > r1g || c0 < r1g - (WINDOW - 1)) sacc[nt][2] = -1e30f;
                if (c1 > r1g || c1 < r1g - (WINDOW - 1)) sacc[nt][3] = -1e30f;
            }
        }

        // ---- online softmax (rows g and g+8; reduce over 4 tig lanes) ----
        float rmax0 = -1e30f, rmax1 = -1e30f;
        #pragma unroll
        for (int nt = 0; nt < 8; nt++) {
            rmax0 = fmaxf(rmax0, fmaxf(sacc[nt][0], sacc[nt][1]));
            rmax1 = fmaxf(rmax1, fmaxf(sacc[nt][2], sacc[nt][3]));
        }
        rmax0 = fmaxf(rmax0, __shfl_xor_sync(0xffffffffu, rmax0, 1, 4));
        rmax0 = fmaxf(rmax0, __shfl_xor_sync(0xffffffffu, rmax0, 2, 4));
        rmax1 = fmaxf(rmax1, __shfl_xor_sync(0xffffffffu, rmax1, 1, 4));
        rmax1 = fmaxf(rmax1, __shfl_xor_sync(0xffffffffu, rmax1, 2, 4));

        float mn0 = fmaxf(m_i[0], rmax0), mn1 = fmaxf(m_i[1], rmax1);
        float cr0 = __expf(m_i[0] - mn0),  cr1 = __expf(m_i[1] - mn1);
        float sum0 = 0.f, sum1 = 0.f;

        #pragma unroll
        for (int nt = 0; nt < 8; nt++) {
            float p00 = __expf(sacc[nt][0] - mn0);
            float p01 = __expf(sacc[nt][1] - mn0);
            float p10 = __expf(sacc[nt][2] - mn1);
            float p11 = __expf(sacc[nt][3] - mn1);
            sum0 += p00 + p01;
            sum1 += p10 + p11;
            int cc = nt * 8 + (tig << 1);
            Ps[(cc    ) * ASPAD + m0 + g]     = f2tf32f(p00);
            Ps[(cc + 1) * ASPAD + m0 + g]     = f2tf32f(p01);
            Ps[(cc    ) * ASPAD + m0 + g + 8] = f2tf32f(p10);
            Ps[(cc + 1) * ASPAD + m0 + g + 8] = f2tf32f(p11);
        }
        sum0 += __shfl_xor_sync(0xffffffffu, sum0, 1, 4);
        sum0 += __shfl_xor_sync(0xffffffffu, sum0, 2, 4);
        sum1 += __shfl_xor_sync(0xffffffffu, sum1, 1, 4);
        sum1 += __shfl_xor_sync(0xffffffffu, sum1, 2, 4);

        l_i[0] = l_i[0] * cr0 + sum0;  m_i[0] = mn0;
        l_i[1] = l_i[1] * cr1 + sum1;  m_i[1] = mn1;

        #pragma unroll
        for (int nt = 0; nt < 8; nt++) {
            oacc[nt][0] *= cr0; oacc[nt][1] *= cr0;
            oacc[nt][2] *= cr1; oacc[nt][3] *= cr1;
        }
        __syncwarp();

        // ---- O += P @ V ----
        #pragma unroll
        for (int ks = 0; ks < 64; ks += 8) {
            uint32_t a0 = __float_as_uint(Ps[(ks + tig    ) * ASPAD + m0 + g]);
            uint32_t a1 = __float_as_uint(Ps[(ks + tig    ) * ASPAD + m0 + g + 8]);
            uint32_t a2 = __float_as_uint(Ps[(ks + tig + 4) * ASPAD + m0 + g]);
            uint32_t a3 = __float_as_uint(Ps[(ks + tig + 4) * ASPAD + m0 + g + 8]);
            #pragma unroll
            for (int nt = 0; nt < 8; nt++) {
                uint32_t b0 = __float_as_uint(Vs[(ks + tig    ) * ASPAD + nt * 8 + g]);
                uint32_t b1 = __float_as_uint(Vs[(ks + tig + 4) * ASPAD + nt * 8 + g]);
                mma_tf32(oacc[nt], a0, a1, a2, a3, b0, b1);
            }
        }
        __syncthreads();   // before next tile overwrites Ks/Vs
    }

    // ---- epilogue: normalize, write g_O ----
    float inv0 = 1.f / l_i[0], inv1 = 1.f / l_i[1];
    #pragma unroll
    for (int nt = 0; nt < 8; nt++) {
        int c = h * 64 + nt * 8 + (tig << 1);
        *(float2*)&g_O[(size_t)r0g * HID + c] =
            make_float2(oacc[nt][0] * inv0, oacc[nt][1] * inv0);
        *(float2*)&g_O[(size_t)r1g * HID + c] =
            make_float2(oacc[nt][2] * inv1, oacc[nt][3] * inv1);
    }
}

// ---------------- launch ----------------
extern "C" void kernel_launch(void* const* d_in, const int* in_sizes, int n_in,
                              void* d_out, int out_size)
{
    const float* X  = (const float*)d_in[0];
    const float* Wq = (const float*)d_in[1];
    const float* Wk = (const float*)d_in[2];
    const float* Wv = (const float*)d_in[3];
    const float* Wo = (const float*)d_in[4];
    float* out = (float*)d_out;

    float *gQ, *gK, *gV, *gO;
    cudaGetSymbolAddress((void**)&gQ, g_Q);
    cudaGetSymbolAddress((void**)&gK, g_K);
    cudaGetSymbolAddress((void**)&gV, g_V);
    cudaGetSymbolAddress((void**)&gO, g_O);

    cudaFuncSetAttribute(attn_tc,
                         cudaFuncAttributeMaxDynamicSharedMemorySize, ATTN_SMEM);

    // QKV projections (tf32 tensor cores)
    gemm_tc<<<dim3(HID / 128, S / 128), 256>>>(X, Wq, gQ, S, HID, HID);
    gemm_tc<<<dim3(KVW / 128, S / 128), 256>>>(X, Wk, gK, S, KVW, HID);
    gemm_tc<<<dim3(KVW / 128, S / 128), 256>>>(X, Wv, gV, S, KVW, HID);

    // RoPE on Q and K
    {
        int total = S * NH * (HD / 2) + S * NKV * (HD / 2);
        rope_kernel<<<(total + 255) / 256, 256>>>();
    }

    // Sliding-window flash attention (tf32 tensor cores)
    attn_tc<<<dim3(S / 64, NH), 128, ATTN_SMEM>>>();

    // Output projection (tf32 tensor cores)
    gemm_tc<<<dim3(HID / 128, S / 128), 256>>>(gO, Wo, out, S, HID, HID);
}

// round 13
// speedup vs baseline: 3.3132x; 1.4738x over previous
#include <cuda_runtime.h>
#include <cuda_bf16.h>
#include <math.h>
#include <stdint.h>

// Problem constants
#define S     2048
#define HID   2048
#define NH    32
#define NKV   8
#define HD    64
#define WINDOW 1024
#define KVW   (NKV*HD)     // 512
#define SCALE 0.125f       // 1/sqrt(64)

// ---------------- scratch (no allocation allowed) ----------------
__device__ float g_Q[S * HID];      // 16 MB
__device__ float g_K[S * KVW];      //  4 MB
__device__ float g_V[S * KVW];      //  4 MB
__device__ float g_O[S * HID];      // 16 MB

// ---------------- tf32 helpers ----------------
__device__ __forceinline__ uint32_t f2tf32(float x) {
    uint32_t u;
    asm("cvt.rna.tf32.f32 %0, %1;" : "=r"(u) : "f"(x));
    return u;
}
__device__ __forceinline__ float f2tf32f(float x) {
    return __uint_as_float(f2tf32(x));
}
__device__ __forceinline__ void mma_tf32(float* c,
    uint32_t a0, uint32_t a1, uint32_t a2, uint32_t a3,
    uint32_t b0, uint32_t b1)
{
    asm volatile(
        "mma.sync.aligned.m16n8k8.row.col.f32.tf32.tf32.f32 "
        "{%0,%1,%2,%3}, {%4,%5,%6,%7}, {%8,%9}, {%0,%1,%2,%3};"
        : "+f"(c[0]), "+f"(c[1]), "+f"(c[2]), "+f"(c[3])
        : "r"(a0), "r"(a1), "r"(a2), "r"(a3), "r"(b0), "r"(b1));
}
__device__ __forceinline__ void cp_async16(uint32_t saddr, const void* gaddr) {
    asm volatile("cp.async.cg.shared.global [%0], [%1], 16;"
                 :: "r"(saddr), "l"(gaddr));
}
__device__ __forceinline__ void cp_commit() {
    asm volatile("cp.async.commit_group;");
}
template <int N>
__device__ __forceinline__ void cp_wait() {
    asm volatile("cp.async.wait_group %0;" :: "n"(N));
}

// ---------------- GEMM: C[M,N] = A[M,K] @ B[K,N], tf32 tensor-core ----
// Block 128x128, BK=16, 256 threads (8 warps, 2x4), warp tile 64x32.
// 4-stage cp.async pipeline. A natural [m][k] pad 20, B natural [k][n] pad 136.
// tf32 cvt at fragment load (numerically identical to cvt-at-STS).
#define STAGES   4
#define A_PAD    20
#define B_PAD    136
#define A_STAGE  (128 * A_PAD)          // floats per A stage (2560)
#define B_STAGE  (16 * B_PAD)           // floats per B stage (2176)
#define GEMM_SMEM ((STAGES * (A_STAGE + B_STAGE)) * 4)   // 75776 bytes

// Shared GEMM body (bm, bn, pointers resolved by caller kernels).
__device__ __forceinline__ void gemm_body(
    const float* __restrict__ A, const float* __restrict__ B,
    float* __restrict__ C, int M, int N, int K, int bm, int bn)
{
    extern __shared__ float smem[];
    float* Asm = smem;                       // [STAGES][128][A_PAD]
    float* Bsm = smem + STAGES * A_STAGE;    // [STAGES][16][B_PAD]

    const int tid  = threadIdx.x;
    const int wid  = tid >> 5, lane = tid & 31;
    const int g    = lane >> 2, tig = lane & 3;
    const int wm   = (wid >> 2) << 6;      // 0 / 64
    const int wn   = (wid & 3) << 5;       // 0,32,64,96

    const float* Ab = A + (size_t)bm * 128 * K;
    const float* Bb = B + bn * 128;

    const int ar = tid >> 1, ac = (tid & 1) << 3;    // A rows 0..127, col 0/8
    const int br = tid >> 4, bc = (tid & 15) << 3;   // B rows 0..15,  col 0..120

    uint32_t a_sbase = (uint32_t)__cvta_generic_to_shared(Asm);
    uint32_t b_sbase = (uint32_t)__cvta_generic_to_shared(Bsm);
    const uint32_t a_saddr0 = a_sbase + (uint32_t)(ar * A_PAD + ac) * 4u;
    const uint32_t b_saddr0 = b_sbase + (uint32_t)(br * B_PAD + bc) * 4u;

    float acc[4][4][4];
    #pragma unroll
    for (int i = 0; i < 4; i++)
        #pragma unroll
        for (int j = 0; j < 4; j++)
            #pragma unroll
            for (int r = 0; r < 4; r++) acc[i][j][r] = 0.f;

    const int NT = K >> 4;

    #pragma unroll
    for (int s = 0; s < STAGES - 1; s++) {
        int k0 = s << 4;
        const float* ga = Ab + (size_t)ar * K + k0 + ac;
        uint32_t sa = a_saddr0 + (uint32_t)(s * A_STAGE) * 4u;
        cp_async16(sa, ga);
        cp_async16(sa + 16u, ga + 4);
        const float* gb = Bb + (size_t)(k0 + br) * N + bc;
        uint32_t sb = b_saddr0 + (uint32_t)(s * B_STAGE) * 4u;
        cp_async16(sb, gb);
        cp_async16(sb + 16u, gb + 4);
        cp_commit();
    }

    for (int kt = 0; kt < NT; kt++) {
        cp_wait<STAGES - 2>();
        __syncthreads();

        const int st = kt & (STAGES - 1);
        const float* As_ = Asm + st * A_STAGE;
        const float* Bs_ = Bsm + st * B_STAGE;

        #pragma unroll
        for (int ks = 0; ks < 16; ks += 8) {
            uint32_t af[4][4], bf[4][2];
            #pragma unroll
            for (int mt = 0; mt < 4; mt++) {
                int m = wm + (mt << 4) + g;
                af[mt][0] = f2tf32(As_[(m    ) * A_PAD + ks + tig    ]);
                af[mt][1] = f2tf32(As_[(m + 8) * A_PAD + ks + tig    ]);
                af[mt][2] = f2tf32(As_[(m    ) * A_PAD + ks + tig + 4]);
                af[mt][3] = f2tf32(As_[(m + 8) * A_PAD + ks + tig + 4]);
            }
            #pragma unroll
            for (int nt = 0; nt < 4; nt++) {
                int n = wn + (nt << 3) + g;
                bf[nt][0] = f2tf32(Bs_[(ks + tig    ) * B_PAD + n]);
                bf[nt][1] = f2tf32(Bs_[(ks + tig + 4) * B_PAD + n]);
            }
            #pragma unroll
            for (int mt = 0; mt < 4; mt++)
                #pragma unroll
                for (int nt = 0; nt < 4; nt++)
                    mma_tf32(acc[mt][nt],
                             af[mt][0], af[mt][1], af[mt][2], af[mt][3],
                             bf[nt][0], bf[nt][1]);
        }

        int nk = kt + STAGES - 1;
        if (nk < NT) {
            int s = nk & (STAGES - 1);
            int k0 = nk << 4;
            const float* ga = Ab + (size_t)ar * K + k0 + ac;
            uint32_t sa = a_saddr0 + (uint32_t)(s * A_STAGE) * 4u;
            cp_async16(sa, ga);
            cp_async16(sa + 16u, ga + 4);
            const float* gb = Bb + (size_t)(k0 + br) * N + bc;
            uint32_t sb = b_saddr0 + (uint32_t)(s * B_STAGE) * 4u;
            cp_async16(sb, gb);
            cp_async16(sb + 16u, gb + 4);
        }
        cp_commit();
    }

    #pragma unroll
    for (int mt = 0; mt < 4; mt++) {
        int r0 = bm * 128 + wm + (mt << 4) + g;
        #pragma unroll
        for (int nt = 0; nt < 4; nt++) {
            int c = bn * 128 + wn + (nt << 3) + (tig << 1);
            *(float2*)&C[(size_t)r0 * N + c] =
                make_float2(acc[mt][nt][0], acc[mt][nt][1]);
            *(float2*)&C[(size_t)(r0 + 8) * N + c] =
                make_float2(acc[mt][nt][2], acc[mt][nt][3]);
        }
    }
}

__global__ __launch_bounds__(256) void gemm_tc(
    const float* __restrict__ A, const float* __restrict__ B,
    float* __restrict__ C, int M, int N, int K)
{
    gemm_body(A, B, C, M, N, K, blockIdx.y, blockIdx.x);
}

// Fused K+V projection: z=0 -> (B0,C0), z=1 -> (B1,C1). One launch, 2x CTAs.
__global__ __launch_bounds__(256) void gemm_tc2(
    const float* __restrict__ A,
    const float* __restrict__ B0, const float* __restrict__ B1,
    float* __restrict__ C0, float* __restrict__ C1,
    int M, int N, int K)
{
    const float* B = blockIdx.z ? B1 : B0;
    float*       C = blockIdx.z ? C1 : C0;
    gemm_body(A, B, C, M, N, K, blockIdx.y, blockIdx.x);
}

// ---------------- RoPE (in place on g_Q and g_K) ----------------
#define LOG2_ROPE_BASE 18.931568569324174f   // log2(500000)
__global__ __launch_bounds__(256) void rope_kernel()
{
    int idx = blockIdx.x * blockDim.x + threadIdx.x;
    const int qtot = S * NH * (HD / 2);
    const int ktot = S * NKV * (HD / 2);
    if (idx >= qtot + ktot) return;

    float* buf; int s, off, d;
    if (idx < qtot) {
        d = idx & 31; int h = (idx >> 5) & 31; s = idx >> 10;
        buf = g_Q; off = s * HID + h * 64 + d;
    } else {
        int j = idx - qtot;
        d = j & 31; int h = (j >> 5) & 7; s = j >> 8;
        buf = g_K; off = s * KVW + h * 64 + d;
    }
    float inv = exp2f(-(float)d * (LOG2_ROPE_BASE / 32.0f));
    float ph  = (float)s * inv;
    float sn, c;
    sincosf(ph, &sn, &c);
    float x1 = buf[off], x2 = buf[off + 32];
    buf[off]      = x1 * c - x2 * sn;
    buf[off + 32] = x2 * c + x1 * sn;
}

// ---------------- Flash attention, sliding window, tf32 tensor-core ---
// grid (S/64, NH), 128 threads (4 warps). Warp w owns q rows 16w..16w+15.
// K/V tiles double-buffered via cp.async in NATURAL [c][d] layout; tf32
// cvt at fragment-load time (bit-identical to cvt-at-STS).
// Pads chosen for conflict-free fragment LDS:
//   Q [r][d] pad 68 (banks 4g+tig), K [c][d] pad 68 (4g+tig),
//   V [c][d] pad 72 (8tig+g), P [c][r] pad 72 (8tig+g).
#define QPAD 68
#define KPAD 68
#define VPAD 72
#define PPAD 72
#define Q_FLOATS  (64 * QPAD)
#define K_STAGE_F (64 * KPAD)
#define V_STAGE_F (64 * VPAD)
#define P_FLOATS  (64 * PPAD)
#define ATTN_SMEM ((Q_FLOATS + 2 * K_STAGE_F + 2 * V_STAGE_F + P_FLOATS) * 4) // 107520

__global__ __launch_bounds__(128) void attn_tc()
{
    extern __shared__ float sm[];
    float* Qs = sm;                                        // [64][QPAD]
    float* Ks = sm + Q_FLOATS;                             // [2][64][KPAD]
    float* Vs = sm + Q_FLOATS + 2 * K_STAGE_F;             // [2][64][VPAD]
    float* Ps = sm + Q_FLOATS + 2 * K_STAGE_F + 2 * V_STAGE_F; // [64][PPAD]

    const int tid = threadIdx.x;
    const int h   = blockIdx.y;
    const int qb  = blockIdx.x << 6;
    const int kvh = h >> 2;                 // NH/NKV = 4
    const int wid = tid >> 5, lane = tid & 31;
    const int g = lane >> 2, tig = lane & 3;
    const int m0 = wid << 4;                // 0,16,32,48

    const uint32_t k_sbase = (uint32_t)__cvta_generic_to_shared(Ks);
    const uint32_t v_sbase = (uint32_t)__cvta_generic_to_shared(Vs);

    // Load Q natural [r][d], prescaled by SCALE, tf32-rounded
    for (int v = tid; v < 64 * 16; v += 128) {
        int r = v >> 4, d4 = (v & 15) << 2;
        float4 q4 = *(const float4*)&g_Q[(size_t)(qb + r) * HID + h * 64 + d4];
        float4 qt;
        qt.x = f2tf32f(q4.x * SCALE); qt.y = f2tf32f(q4.y * SCALE);
        qt.z = f2tf32f(q4.z * SCALE); qt.w = f2tf32f(q4.w * SCALE);
        *(float4*)&Qs[r * QPAD + d4] = qt;
    }

    float m_i[2] = {-1e30f, -1e30f};
    float l_i[2] = {0.f, 0.f};
    float oacc[8][4];
    #pragma unroll
    for (int nt = 0; nt < 8; nt++)
        #pragma unroll
        for (int r = 0; r < 4; r++) oacc[nt][r] = 0.f;

    const int t0 = max(0, qb - (WINDOW - 1)) >> 6;
    const int t1 = qb >> 6;
    const int r0g = qb + m0 + g, r1g = r0g + 8;

    // ---- prologue: issue tile t0 into stage 0 ----
    {
        const int kb = t0 << 6;
        #pragma unroll
        for (int i = 0; i < 8; i++) {
            int v = tid + i * 128;              // 0..1023
            int c = v >> 4, j4 = (v & 15) << 2;
            size_t gofs = (size_t)(kb + c) * KVW + kvh * 64 + j4;
            cp_async16(k_sbase + (uint32_t)(c * KPAD + j4) * 4u, &g_K[gofs]);
            cp_async16(v_sbase + (uint32_t)(c * VPAD + j4) * 4u, &g_V[gofs]);
        }
        cp_commit();
    }

    for (int t = t0; t <= t1; ++t) {
        const int st = (t - t0) & 1;
        const int kb = t << 6;

        // issue next tile into the other stage
        if (t < t1) {
            const int kbn = (t + 1) << 6;
            const int stn = st ^ 1;
            #pragma unroll
            for (int i = 0; i < 8; i++) {
                int v = tid + i * 128;
                int c = v >> 4, j4 = (v & 15) << 2;
                size_t gofs = (size_t)(kbn + c) * KVW + kvh * 64 + j4;
                cp_async16(k_sbase + (uint32_t)(stn * K_STAGE_F + c * KPAD + j4) * 4u, &g_K[gofs]);
                cp_async16(v_sbase + (uint32_t)(stn * V_STAGE_F + c * VPAD + j4) * 4u, &g_V[gofs]);
            }
        }
        cp_commit();
        cp_wait<1>();        // tile t complete (only the t+1 group may remain)
        __syncthreads();

        const float* Kst = Ks + st * K_STAGE_F;
        const float* Vst = Vs + st * V_STAGE_F;

        // ---- S = Q @ K^T (Q pre-scaled) ----
        float sacc[8][4];
        #pragma unroll
        for (int nt = 0; nt < 8; nt++)
            #pragma unroll
            for (int r = 0; r < 4; r++) sacc[nt][r] = 0.f;

        #pragma unroll
        for (int ks = 0; ks < 64; ks += 8) {
            uint32_t a0 = f2tf32(Qs[(m0 + g    ) * QPAD + ks + tig    ]);
            uint32_t a1 = f2tf32(Qs[(m0 + g + 8) * QPAD + ks + tig    ]);
            uint32_t a2 = f2tf32(Qs[(m0 + g    ) * QPAD + ks + tig + 4]);
            uint32_t a3 = f2tf32(Qs[(m0 + g + 8) * QPAD + ks + tig + 4]);
            #pragma unroll
            for (int nt = 0; nt < 8; nt++) {
                uint32_t b0 = f2tf32(Kst[(nt * 8 + g) * KPAD + ks + tig    ]);
                uint32_t b1 = f2tf32(Kst[(nt * 8 + g) * KPAD + ks + tig + 4]);
                mma_tf32(sacc[nt], a0, a1, a2, a3, b0, b1);
            }
        }

        // ---- mask (boundary tiles only) ----
        if ((t == t1) || (kb < qb - 960)) {
            #pragma unroll
            for (int nt = 0; nt < 8; nt++) {
                int c0 = kb + nt * 8 + (tig << 1), c1 = c0 + 1;
                if (c0 > r0g || c0 < r0g - (WINDOW - 1)) sacc[nt][0] = -1e30f;
                if (c1 > r0g || c1 < r0g - (WINDOW - 1)) sacc[nt][1] = -1e30f;
                if (c0 > r1g || c0 < r1g - (WINDOW - 1)) sacc[nt][2] = -1e30f;
                if (c1 > r1g || c1 < r1g - (WINDOW - 1)) sacc[nt][3] = -1e30f;
            }
        }

        // ---- online softmax (rows g and g+8; reduce over 4 tig lanes) ----
        float rmax0 = -1e30f, rmax1 = -1e30f;
        #pragma unroll
        for (int nt = 0; nt < 8; nt++) {
            rmax0 = fmaxf(rmax0, fmaxf(sacc[nt][0], sacc[nt][1]));
            rmax1 = fmaxf(rmax1, fmaxf(sacc[nt][2], sacc[nt][3]));
        }
        rmax0 = fmaxf(rmax0, __shfl_xor_sync(0xffffffffu, rmax0, 1, 4));
        rmax0 = fmaxf(rmax0, __shfl_xor_sync(0xffffffffu, rmax0, 2, 4));
        rmax1 = fmaxf(rmax1, __shfl_xor_sync(0xffffffffu, rmax1, 1, 4));
        rmax1 = fmaxf(rmax1, __shfl_xor_sync(0xffffffffu, rmax1, 2, 4));

        float mn0 = fmaxf(m_i[0], rmax0), mn1 = fmaxf(m_i[1], rmax1);
        float cr0 = __expf(m_i[0] - mn0),  cr1 = __expf(m_i[1] - mn1);
        float sum0 = 0.f, sum1 = 0.f;

        #pragma unroll
        for (int nt = 0; nt < 8; nt++) {
            float p00 = __expf(sacc[nt][0] - mn0);
            float p01 = __expf(sacc[nt][1] - mn0);
            float p10 = __expf(sacc[nt][2] - mn1);
            float p11 = __expf(sacc[nt][3] - mn1);
            sum0 += p00 + p01;
            sum1 += p10 + p11;
            int cc = nt * 8 + (tig << 1);
            Ps[(cc    ) * PPAD + m0 + g]     = f2tf32f(p00);
            Ps[(cc + 1) * PPAD + m0 + g]     = f2tf32f(p01);
            Ps[(cc    ) * PPAD + m0 + g + 8] = f2tf32f(p10);
            Ps[(cc + 1) * PPAD + m0 + g + 8] = f2tf32f(p11);
        }
        sum0 += __shfl_xor_sync(0xffffffffu, sum0, 1, 4);
        sum0 += __shfl_xor_sync(0xffffffffu, sum0, 2, 4);
        sum1 += __shfl_xor_sync(0xffffffffu, sum1, 1, 4);
        sum1 += __shfl_xor_sync(0xffffffffu, sum1, 2, 4);

        l_i[0] = l_i[0] * cr0 + sum0;  m_i[0] = mn0;
        l_i[1] = l_i[1] * cr1 + sum1;  m_i[1] = mn1;

        #pragma unroll
        for (int nt = 0; nt < 8; nt++) {
            oacc[nt][0] *= cr0; oacc[nt][1] *= cr0;
            oacc[nt][2] *= cr1; oacc[nt][3] *= cr1;
        }
        __syncwarp();

        // ---- O += P @ V ----
        #pragma unroll
        for (int ks = 0; ks < 64; ks += 8) {
            uint32_t a0 = __float_as_uint(Ps[(ks + tig    ) * PPAD + m0 + g]);
            uint32_t a1 = __float_as_uint(Ps[(ks + tig    ) * PPAD + m0 + g + 8]);
            uint32_t a2 = __float_as_uint(Ps[(ks + tig + 4) * PPAD + m0 + g]);
            uint32_t a3 = __float_as_uint(Ps[(ks + tig + 4) * PPAD + m0 + g + 8]);
            #pragma unroll
            for (int nt = 0; nt < 8; nt++) {
                uint32_t b0 = f2tf32(Vst[(ks + tig    ) * VPAD + nt * 8 + g]);
                uint32_t b1 = f2tf32(Vst[(ks + tig + 4) * VPAD + nt * 8 + g]);
                mma_tf32(oacc[nt], a0, a1, a2, a3, b0, b1);
            }
        }
        __syncthreads();   // compute done before next iter's cp.async overwrites
    }

    // ---- epilogue: normalize, write g_O ----
    float inv0 = 1.f / l_i[0], inv1 = 1.f / l_i[1];
    #pragma unroll
    for (int nt = 0; nt < 8; nt++) {
        int c = h * 64 + nt * 8 + (tig << 1);
        *(float2*)&g_O[(size_t)r0g * HID + c] =
            make_float2(oacc[nt][0] * inv0, oacc[nt][1] * inv0);
        *(float2*)&g_O[(size_t)r1g * HID + c] =
            make_float2(oacc[nt][2] * inv1, oacc[nt][3] * inv1);
    }
}

// ---------------- launch ----------------
extern "C" void kernel_launch(void* const* d_in, const int* in_sizes, int n_in,
                              void* d_out, int out_size)
{
    const float* X  = (const float*)d_in[0];
    const float* Wq = (const float*)d_in[1];
    const float* Wk = (const float*)d_in[2];
    const float* Wv = (const float*)d_in[3];
    const float* Wo = (const float*)d_in[4];
    float* out = (float*)d_out;

    float *gQ, *gK, *gV, *gO;
    cudaGetSymbolAddress((void**)&gQ, g_Q);
    cudaGetSymbolAddress((void**)&gK, g_K);
    cudaGetSymbolAddress((void**)&gV, g_V);
    cudaGetSymbolAddress((void**)&gO, g_O);

    cudaFuncSetAttribute(gemm_tc,
                         cudaFuncAttributeMaxDynamicSharedMemorySize, GEMM_SMEM);
    cudaFuncSetAttribute(gemm_tc2,
                         cudaFuncAttributeMaxDynamicSharedMemorySize, GEMM_SMEM);
    cudaFuncSetAttribute(attn_tc,
                         cudaFuncAttributeMaxDynamicSharedMemorySize, ATTN_SMEM);

    // Q projection (tf32 tensor cores, cp.async pipelined)
    gemm_tc<<<dim3(HID / 128, S / 128), 256, GEMM_SMEM>>>(X, Wq, gQ, S, HID, HID);
    // K + V projections fused in one launch (z selects weight/output)
    gemm_tc2<<<dim3(KVW / 128, S / 128, 2), 256, GEMM_SMEM>>>(X, Wk, Wv, gK, gV, S, KVW, HID);

    // RoPE on Q and K
    {
        int total = S * NH * (HD / 2) + S * NKV * (HD / 2);
        rope_kernel<<<(total + 255) / 256, 256>>>();
    }

    // Sliding-window flash attention (tf32 tensor cores, cp.async K/V)
    attn_tc<<<dim3(S / 64, NH), 128, ATTN_SMEM>>>();

    // Output projection (tf32 tensor cores)
    gemm_tc<<<dim3(HID / 128, S / 128), 256, GEMM_SMEM>>>(gO, Wo, out, S, HID, HID);
}

// round 17
// speedup vs baseline: 3.7677x; 1.1372x over previous
#include <cuda_runtime.h>
#include <cuda_bf16.h>
#include <math.h>
#include <stdint.h>

// Problem constants
#define S     2048
#define HID   2048
#define NH    32
#define NKV   8
#define HD    64
#define WINDOW 1024
#define KVW   (NKV*HD)     // 512
#define SCALE 0.125f       // 1/sqrt(64)

// ---------------- scratch (no allocation allowed) ----------------
__device__ float g_Q[S * HID];        // 16 MB
__device__ float g_K[S * KVW];        //  4 MB
__device__ float g_V[S * KVW];        //  4 MB
__device__ float g_O[S * HID];        // 16 MB (tf32-rounded by attn epilogue)
__device__ float g_Xt[S * HID];       // 16 MB tf32-rounded X
__device__ float g_Wqt[HID * HID];    // 16 MB tf32-rounded Wq
__device__ float g_Wkt[HID * KVW];    //  4 MB tf32-rounded Wk
__device__ float g_Wvt[HID * KVW];    //  4 MB tf32-rounded Wv
__device__ float g_Wot[HID * HID];    // 16 MB tf32-rounded Wo

// ---------------- tf32 helpers ----------------
__device__ __forceinline__ uint32_t f2tf32(float x) {
    uint32_t u;
    asm("cvt.rna.tf32.f32 %0, %1;" : "=r"(u) : "f"(x));
    return u;
}
__device__ __forceinline__ float f2tf32f(float x) {
    return __uint_as_float(f2tf32(x));
}
__device__ __forceinline__ void mma_tf32(float* c,
    uint32_t a0, uint32_t a1, uint32_t a2, uint32_t a3,
    uint32_t b0, uint32_t b1)
{
    asm volatile(
        "mma.sync.aligned.m16n8k8.row.col.f32.tf32.tf32.f32 "
        "{%0,%1,%2,%3}, {%4,%5,%6,%7}, {%8,%9}, {%0,%1,%2,%3};"
        : "+f"(c[0]), "+f"(c[1]), "+f"(c[2]), "+f"(c[3])
        : "r"(a0), "r"(a1), "r"(a2), "r"(a3), "r"(b0), "r"(b1));
}
__device__ __forceinline__ void cp_async16(uint32_t saddr, const void* gaddr) {
    asm volatile("cp.async.cg.shared.global [%0], [%1], 16;"
                 :: "r"(saddr), "l"(gaddr));
}
__device__ __forceinline__ void cp_commit() {
    asm volatile("cp.async.commit_group;");
}
template <int N>
__device__ __forceinline__ void cp_wait() {
    asm volatile("cp.async.wait_group %0;" :: "n"(N));
}

// ---------------- pre-convert inputs/weights to tf32 (idempotent) ----
__global__ __launch_bounds__(256) void cvt_pre(
    const float* __restrict__ X,  const float* __restrict__ Wq,
    const float* __restrict__ Wk, const float* __restrict__ Wv,
    const float* __restrict__ Wo)
{
    const int NX = S * HID / 4, NQ = HID * HID / 4, NK = HID * KVW / 4;
    int j = blockIdx.x * blockDim.x + threadIdx.x;
    const float* src; float* dst;
    if (j < NX)               { src = X;  dst = g_Xt; }
    else if ((j -= NX) < NQ)  { src = Wq; dst = g_Wqt; }
    else if ((j -= NQ) < NK)  { src = Wk; dst = g_Wkt; }
    else if ((j -= NK) < NK)  { src = Wv; dst = g_Wvt; }
    else if ((j -= NK) < NQ)  { src = Wo; dst = g_Wot; }
    else return;
    float4 v = ((const float4*)src)[j];
    v.x = f2tf32f(v.x); v.y = f2tf32f(v.y);
    v.z = f2tf32f(v.z); v.w = f2tf32f(v.w);
    ((float4*)dst)[j] = v;
}

// ---------------- GEMM: C[M,N] = A[M,K] @ B[K,N], tf32 tensor-core ----
// Inputs are PRE-ROUNDED to tf32 -> fragment loads are plain LDS (no cvt).
#define STAGES   4
#define A_PAD    20
#define B_PAD    136
#define A_STAGE  (128 * A_PAD)
#define B_STAGE  (16 * B_PAD)
#define GEMM_SMEM ((STAGES * (A_STAGE + B_STAGE)) * 4)   // 75776 bytes

__device__ __forceinline__ void gemm_body(
    const float* __restrict__ A, const float* __restrict__ B,
    float* __restrict__ C, int M, int N, int K, int bm, int bn, bool round_out)
{
    extern __shared__ float smem[];
    float* Asm = smem;                       // [STAGES][128][A_PAD]
    float* Bsm = smem + STAGES * A_STAGE;    // [STAGES][16][B_PAD]

    const int tid  = threadIdx.x;
    const int wid  = tid >> 5, lane = tid & 31;
    const int g    = lane >> 2, tig = lane & 3;
    const int wm   = (wid >> 2) << 6;
    const int wn   = (wid & 3) << 5;

    const float* Ab = A + (size_t)bm * 128 * K;
    const float* Bb = B + bn * 128;

    const int ar = tid >> 1, ac = (tid & 1) << 3;
    const int br = tid >> 4, bc = (tid & 15) << 3;

    uint32_t a_sbase = (uint32_t)__cvta_generic_to_shared(Asm);
    uint32_t b_sbase = (uint32_t)__cvta_generic_to_shared(Bsm);
    const uint32_t a_saddr0 = a_sbase + (uint32_t)(ar * A_PAD + ac) * 4u;
    const uint32_t b_saddr0 = b_sbase + (uint32_t)(br * B_PAD + bc) * 4u;

    float acc[4][4][4];
    #pragma unroll
    for (int i = 0; i < 4; i++)
        #pragma unroll
        for (int j = 0; j < 4; j++)
            #pragma unroll
            for (int r = 0; r < 4; r++) acc[i][j][r] = 0.f;

    const int NT = K >> 4;

    #pragma unroll
    for (int s = 0; s < STAGES - 1; s++) {
        int k0 = s << 4;
        const float* ga = Ab + (size_t)ar * K + k0 + ac;
        uint32_t sa = a_saddr0 + (uint32_t)(s * A_STAGE) * 4u;
        cp_async16(sa, ga);
        cp_async16(sa + 16u, ga + 4);
        const float* gb = Bb + (size_t)(k0 + br) * N + bc;
        uint32_t sb = b_saddr0 + (uint32_t)(s * B_STAGE) * 4u;
        cp_async16(sb, gb);
        cp_async16(sb + 16u, gb + 4);
        cp_commit();
    }

    for (int kt = 0; kt < NT; kt++) {
        cp_wait<STAGES - 2>();
        __syncthreads();

        const int st = kt & (STAGES - 1);
        const float* As_ = Asm + st * A_STAGE;
        const float* Bs_ = Bsm + st * B_STAGE;

        #pragma unroll
        for (int ks = 0; ks < 16; ks += 8) {
            uint32_t af[4][4], bf[4][2];
            #pragma unroll
            for (int mt = 0; mt < 4; mt++) {
                int m = wm + (mt << 4) + g;
                af[mt][0] = __float_as_uint(As_[(m    ) * A_PAD + ks + tig    ]);
                af[mt][1] = __float_as_uint(As_[(m + 8) * A_PAD + ks + tig    ]);
                af[mt][2] = __float_as_uint(As_[(m    ) * A_PAD + ks + tig + 4]);
                af[mt][3] = __float_as_uint(As_[(m + 8) * A_PAD + ks + tig + 4]);
            }
            #pragma unroll
            for (int nt = 0; nt < 4; nt++) {
                int n = wn + (nt << 3) + g;
                bf[nt][0] = __float_as_uint(Bs_[(ks + tig    ) * B_PAD + n]);
                bf[nt][1] = __float_as_uint(Bs_[(ks + tig + 4) * B_PAD + n]);
            }
            #pragma unroll
            for (int mt = 0; mt < 4; mt++)
                #pragma unroll
                for (int nt = 0; nt < 4; nt++)
                    mma_tf32(acc[mt][nt],
                             af[mt][0], af[mt][1], af[mt][2], af[mt][3],
                             bf[nt][0], bf[nt][1]);
        }

        int nk = kt + STAGES - 1;
        if (nk < NT) {
            int s = nk & (STAGES - 1);
            int k0 = nk << 4;
            const float* ga = Ab + (size_t)ar * K + k0 + ac;
            uint32_t sa = a_saddr0 + (uint32_t)(s * A_STAGE) * 4u;
            cp_async16(sa, ga);
            cp_async16(sa + 16u, ga + 4);
            const float* gb = Bb + (size_t)(k0 + br) * N + bc;
            uint32_t sb = b_saddr0 + (uint32_t)(s * B_STAGE) * 4u;
            cp_async16(sb, gb);
            cp_async16(sb + 16u, gb + 4);
        }
        cp_commit();
    }

    #pragma unroll
    for (int mt = 0; mt < 4; mt++) {
        int r0 = bm * 128 + wm + (mt << 4) + g;
        #pragma unroll
        for (int nt = 0; nt < 4; nt++) {
            int c = bn * 128 + wn + (nt << 3) + (tig << 1);
            float v0 = acc[mt][nt][0], v1 = acc[mt][nt][1];
            float v2 = acc[mt][nt][2], v3 = acc[mt][nt][3];
            if (round_out) {
                v0 = f2tf32f(v0); v1 = f2tf32f(v1);
                v2 = f2tf32f(v2); v3 = f2tf32f(v3);
            }
            *(float2*)&C[(size_t)r0 * N + c]       = make_float2(v0, v1);
            *(float2*)&C[(size_t)(r0 + 8) * N + c] = make_float2(v2, v3);
        }
    }
}

__global__ __launch_bounds__(256, 2) void gemm_tc(
    const float* __restrict__ A, const float* __restrict__ B,
    float* __restrict__ C, int M, int N, int K)
{
    gemm_body(A, B, C, M, N, K, blockIdx.y, blockIdx.x, false);
}

// Fused K+V projection: z=0 -> K (unrounded; rope rounds), z=1 -> V (rounded).
__global__ __launch_bounds__(256, 2) void gemm_tc2(
    const float* __restrict__ A,
    const float* __restrict__ B0, const float* __restrict__ B1,
    float* __restrict__ C0, float* __restrict__ C1,
    int M, int N, int K)
{
    const float* B = blockIdx.z ? B1 : B0;
    float*       C = blockIdx.z ? C1 : C0;
    gemm_body(A, B, C, M, N, K, blockIdx.y, blockIdx.x, blockIdx.z != 0);
}

// ---------------- RoPE (in place; writes tf32-rounded Q and K) --------
#define LOG2_ROPE_BASE 18.931568569324174f   // log2(500000)
__global__ __launch_bounds__(256) void rope_kernel()
{
    int idx = blockIdx.x * blockDim.x + threadIdx.x;
    const int qtot = S * NH * (HD / 2);
    const int ktot = S * NKV * (HD / 2);
    if (idx >= qtot + ktot) return;

    float* buf; int s, off, d;
    if (idx < qtot) {
        d = idx & 31; int h = (idx >> 5) & 31; s = idx >> 10;
        buf = g_Q; off = s * HID + h * 64 + d;
    } else {
        int j = idx - qtot;
        d = j & 31; int h = (j >> 5) & 7; s = j >> 8;
        buf = g_K; off = s * KVW + h * 64 + d;
    }
    float inv = exp2f(-(float)d * (LOG2_ROPE_BASE / 32.0f));
    float ph  = (float)s * inv;
    float sn, c;
    sincosf(ph, &sn, &c);
    float x1 = buf[off], x2 = buf[off + 32];
    buf[off]      = f2tf32f(x1 * c - x2 * sn);
    buf[off + 32] = f2tf32f(x2 * c + x1 * sn);
}

// ---------------- Flash attention, sliding window, tf32 tensor-core ---
// All inputs (Q,K,V) arrive tf32-pre-rounded -> no cvt in inner loops.
#define QPAD 68
#define KPAD 68
#define VPAD 72
#define PPAD 72
#define Q_FLOATS  (64 * QPAD)
#define K_STAGE_F (64 * KPAD)
#define V_STAGE_F (64 * VPAD)
#define P_FLOATS  (64 * PPAD)
#define ATTN_SMEM ((Q_FLOATS + 2 * K_STAGE_F + 2 * V_STAGE_F + P_FLOATS) * 4) // 107520

__global__ __launch_bounds__(128) void attn_tc()
{
    extern __shared__ float sm[];
    float* Qs = sm;                                        // [64][QPAD]
    float* Ks = sm + Q_FLOATS;                             // [2][64][KPAD]
    float* Vs = sm + Q_FLOATS + 2 * K_STAGE_F;             // [2][64][VPAD]
    float* Ps = sm + Q_FLOATS + 2 * K_STAGE_F + 2 * V_STAGE_F; // [64][PPAD]

    const int tid = threadIdx.x;
    const int h   = blockIdx.y;
    const int qb  = blockIdx.x << 6;
    const int kvh = h >> 2;
    const int wid = tid >> 5, lane = tid & 31;
    const int g = lane >> 2, tig = lane & 3;
    const int m0 = wid << 4;

    const uint32_t k_sbase = (uint32_t)__cvta_generic_to_shared(Ks);
    const uint32_t v_sbase = (uint32_t)__cvta_generic_to_shared(Vs);

    // Q already tf32-rounded by rope; *SCALE (2^-3) is exact -> still tf32.
    for (int v = tid; v < 64 * 16; v += 128) {
        int r = v >> 4, d4 = (v & 15) << 2;
        float4 q4 = *(const float4*)&g_Q[(size_t)(qb + r) * HID + h * 64 + d4];
        q4.x *= SCALE; q4.y *= SCALE; q4.z *= SCALE; q4.w *= SCALE;
        *(float4*)&Qs[r * QPAD + d4] = q4;
    }

    float m_i[2] = {-1e30f, -1e30f};
    float l_i[2] = {0.f, 0.f};
    float oacc[8][4];
    #pragma unroll
    for (int nt = 0; nt < 8; nt++)
        #pragma unroll
        for (int r = 0; r < 4; r++) oacc[nt][r] = 0.f;

    const int t0 = max(0, qb - (WINDOW - 1)) >> 6;
    const int t1 = qb >> 6;
    const int r0g = qb + m0 + g, r1g = r0g + 8;

    {
        const int kb = t0 << 6;
        #pragma unroll
        for (int i = 0; i < 8; i++) {
            int v = tid + i * 128;
            int c = v >> 4, j4 = (v & 15) << 2;
            size_t gofs = (size_t)(kb + c) * KVW + kvh * 64 + j4;
            cp_async16(k_sbase + (uint32_t)(c * KPAD + j4) * 4u, &g_K[gofs]);
            cp_async16(v_sbase + (uint32_t)(c * VPAD + j4) * 4u, &g_V[gofs]);
        }
        cp_commit();
    }

    for (int t = t0; t <= t1; ++t) {
        const int st = (t - t0) & 1;
        const int kb = t << 6;

        if (t < t1) {
            const int kbn = (t + 1) << 6;
            const int stn = st ^ 1;
            #pragma unroll
            for (int i = 0; i < 8; i++) {
                int v = tid + i * 128;
                int c = v >> 4, j4 = (v & 15) << 2;
                size_t gofs = (size_t)(kbn + c) * KVW + kvh * 64 + j4;
                cp_async16(k_sbase + (uint32_t)(stn * K_STAGE_F + c * KPAD + j4) * 4u, &g_K[gofs]);
                cp_async16(v_sbase + (uint32_t)(stn * V_STAGE_F + c * VPAD + j4) * 4u, &g_V[gofs]);
            }
        }
        cp_commit();
        cp_wait<1>();
        __syncthreads();

        const float* Kst = Ks + st * K_STAGE_F;
        const float* Vst = Vs + st * V_STAGE_F;

        // ---- S = Q @ K^T ----
        float sacc[8][4];
        #pragma unroll
        for (int nt = 0; nt < 8; nt++)
            #pragma unroll
            for (int r = 0; r < 4; r++) sacc[nt][r] = 0.f;

        #pragma unroll
        for (int ks = 0; ks < 64; ks += 8) {
            uint32_t a0 = __float_as_uint(Qs[(m0 + g    ) * QPAD + ks + tig    ]);
            uint32_t a1 = __float_as_uint(Qs[(m0 + g + 8) * QPAD + ks + tig    ]);
            uint32_t a2 = __float_as_uint(Qs[(m0 + g    ) * QPAD + ks + tig + 4]);
            uint32_t a3 = __float_as_uint(Qs[(m0 + g + 8) * QPAD + ks + tig + 4]);
            #pragma unroll
            for (int nt = 0; nt < 8; nt++) {
                uint32_t b0 = __float_as_uint(Kst[(nt * 8 + g) * KPAD + ks + tig    ]);
                uint32_t b1 = __float_as_uint(Kst[(nt * 8 + g) * KPAD + ks + tig + 4]);
                mma_tf32(sacc[nt], a0, a1, a2, a3, b0, b1);
            }
        }

        // ---- mask (boundary tiles only) ----
        if ((t == t1) || (kb < qb - 960)) {
            #pragma unroll
            for (int nt = 0; nt < 8; nt++) {
                int c0 = kb + nt * 8 + (tig << 1), c1 = c0 + 1;
                if (c0 > r0g || c0 < r0g - (WINDOW - 1)) sacc[nt][0] = -1e30f;
                if (c1 > r0g || c1 < r0g - (WINDOW - 1)) sacc[nt][1] = -1e30f;
                if (c0 > r1g || c0 < r1g - (WINDOW - 1)) sacc[nt][2] = -1e30f;
                if (c1 > r1g || c1 < r1g - (WINDOW - 1)) sacc[nt][3] = -1e30f;
            }
        }

        // ---- online softmax ----
        float rmax0 = -1e30f, rmax1 = -1e30f;
        #pragma unroll
        for (int nt = 0; nt < 8; nt++) {
            rmax0 = fmaxf(rmax0, fmaxf(sacc[nt][0], sacc[nt][1]));
            rmax1 = fmaxf(rmax1, fmaxf(sacc[nt][2], sacc[nt][3]));
        }
        rmax0 = fmaxf(rmax0, __shfl_xor_sync(0xffffffffu, rmax0, 1, 4));
        rmax0 = fmaxf(rmax0, __shfl_xor_sync(0xffffffffu, rmax0, 2, 4));
        rmax1 = fmaxf(rmax1, __shfl_xor_sync(0xffffffffu, rmax1, 1, 4));
        rmax1 = fmaxf(rmax1, __shfl_xor_sync(0xffffffffu, rmax1, 2, 4));

        float mn0 = fmaxf(m_i[0], rmax0), mn1 = fmaxf(m_i[1], rmax1);
        float cr0 = __expf(m_i[0] - mn0),  cr1 = __expf(m_i[1] - mn1);
        float sum0 = 0.f, sum1 = 0.f;

        #pragma unroll
        for (int nt = 0; nt < 8; nt++) {
            float p00 = __expf(sacc[nt][0] - mn0);
            float p01 = __expf(sacc[nt][1] - mn0);
            float p10 = __expf(sacc[nt][2] - mn1);
            float p11 = __expf(sacc[nt][3] - mn1);
            sum0 += p00 + p01;
            sum1 += p10 + p11;
            int cc = nt * 8 + (tig << 1);
            Ps[(cc    ) * PPAD + m0 + g]     = f2tf32f(p00);
            Ps[(cc + 1) * PPAD + m0 + g]     = f2tf32f(p01);
            Ps[(cc    ) * PPAD + m0 + g + 8] = f2tf32f(p10);
            Ps[(cc + 1) * PPAD + m0 + g + 8] = f2tf32f(p11);
        }
        sum0 += __shfl_xor_sync(0xffffffffu, sum0, 1, 4);
        sum0 += __shfl_xor_sync(0xffffffffu, sum0, 2, 4);
        sum1 += __shfl_xor_sync(0xffffffffu, sum1, 1, 4);
        sum1 += __shfl_xor_sync(0xffffffffu, sum1, 2, 4);

        l_i[0] = l_i[0] * cr0 + sum0;  m_i[0] = mn0;
        l_i[1] = l_i[1] * cr1 + sum1;  m_i[1] = mn1;

        #pragma unroll
        for (int nt = 0; nt < 8; nt++) {
            oacc[nt][0] *= cr0; oacc[nt][1] *= cr0;
            oacc[nt][2] *= cr1; oacc[nt][3] *= cr1;
        }
        __syncwarp();

        // ---- O += P @ V ----
        #pragma unroll
        for (int ks = 0; ks < 64; ks += 8) {
            uint32_t a0 = __float_as_uint(Ps[(ks + tig    ) * PPAD + m0 + g]);
            uint32_t a1 = __float_as_uint(Ps[(ks + tig    ) * PPAD + m0 + g + 8]);
            uint32_t a2 = __float_as_uint(Ps[(ks + tig + 4) * PPAD + m0 + g]);
            uint32_t a3 = __float_as_uint(Ps[(ks + tig + 4) * PPAD + m0 + g + 8]);
            #pragma unroll
            for (int nt = 0; nt < 8; nt++) {
                uint32_t b0 = __float_as_uint(Vst[(ks + tig    ) * VPAD + nt * 8 + g]);
                uint32_t b1 = __float_as_uint(Vst[(ks + tig + 4) * VPAD + nt * 8 + g]);
                mma_tf32(oacc[nt], a0, a1, a2, a3, b0, b1);
            }
        }
        __syncthreads();
    }

    // ---- epilogue: normalize, tf32-round (O-proj would round anyway) ----
    float inv0 = 1.f / l_i[0], inv1 = 1.f / l_i[1];
    #pragma unroll
    for (int nt = 0; nt < 8; nt++) {
        int c = h * 64 + nt * 8 + (tig << 1);
        *(float2*)&g_O[(size_t)r0g * HID + c] =
            make_float2(f2tf32f(oacc[nt][0] * inv0), f2tf32f(oacc[nt][1] * inv0));
        *(float2*)&g_O[(size_t)r1g * HID + c] =
            make_float2(f2tf32f(oacc[nt][2] * inv1), f2tf32f(oacc[nt][3] * inv1));
    }
}

// ---------------- launch ----------------
extern "C" void kernel_launch(void* const* d_in, const int* in_sizes, int n_in,
                              void* d_out, int out_size)
{
    const float* X  = (const float*)d_in[0];
    const float* Wq = (const float*)d_in[1];
    const float* Wk = (const float*)d_in[2];
    const float* Wv = (const float*)d_in[3];
    const float* Wo = (const float*)d_in[4];
    float* out = (float*)d_out;

    float *gQ, *gK, *gV, *gO, *gXt, *gWqt, *gWkt, *gWvt, *gWot;
    cudaGetSymbolAddress((void**)&gQ,  g_Q);
    cudaGetSymbolAddress((void**)&gK,  g_K);
    cudaGetSymbolAddress((void**)&gV,  g_V);
    cudaGetSymbolAddress((void**)&gO,  g_O);
    cudaGetSymbolAddress((void**)&gXt, g_Xt);
    cudaGetSymbolAddress((void**)&gWqt, g_Wqt);
    cudaGetSymbolAddress((void**)&gWkt, g_Wkt);
    cudaGetSymbolAddress((void**)&gWvt, g_Wvt);
    cudaGetSymbolAddress((void**)&gWot, g_Wot);

    cudaFuncSetAttribute(gemm_tc,
                         cudaFuncAttributeMaxDynamicSharedMemorySize, GEMM_SMEM);
    cudaFuncSetAttribute(gemm_tc2,
                         cudaFuncAttributeMaxDynamicSharedMemorySize, GEMM_SMEM);
    cudaFuncSetAttribute(attn_tc,
                         cudaFuncAttributeMaxDynamicSharedMemorySize, ATTN_SMEM);

    // Pre-round X + weights to tf32 (idempotent w.r.t. later mma rounding)
    {
        const int total4 = (S * HID + 2 * HID * HID + 2 * HID * KVW) / 4;
        cvt_pre<<<(total4 + 255) / 256, 256>>>(X, Wq, Wk, Wv, Wo);
    }

    // Q projection
    gemm_tc<<<dim3(HID / 128, S / 128), 256, GEMM_SMEM>>>(gXt, gWqt, gQ, S, HID, HID);
    // K + V projections fused (z=1 -> V, rounded at epilogue)
    gemm_tc2<<<dim3(KVW / 128, S / 128, 2), 256, GEMM_SMEM>>>(gXt, gWkt, gWvt, gK, gV, S, KVW, HID);

    // RoPE on Q and K (writes tf32-rounded)
    {
        int total = S * NH * (HD / 2) + S * NKV * (HD / 2);
        rope_kernel<<<(total + 255) / 256, 256>>>();
    }

    // Sliding-window flash attention
    attn_tc<<<dim3(S / 64, NH), 128, ATTN_SMEM>>>();

    // Output projection (full-fp32 output)
    gemm_tc<<<dim3(HID / 128, S / 128), 256, GEMM_SMEM>>>(gO, gWot, out, S, HID, HID);
}